// round 2
// baseline (speedup 1.0000x reference)
#include <cuda_runtime.h>

#define N_CELLS   776
#define N_ANCHORS 3
#define N_CH      7
#define CONF_THRESH 0.8f
#define NO_OBJECT   0.5f

__global__ void __launch_bounds__(1024, 1)
yolo_loss_kernel(const float* __restrict__ pred,
                 const float* __restrict__ label,
                 float* __restrict__ out)
{
    // Broadcast label into registers (L1/L2 hit, all threads same address)
    const float l0 = label[0], l1 = label[1], l2 = label[2], l3 = label[3];
    const float l4 = label[4], l5 = label[5], l6 = label[6];

    const int cell = threadIdx.x;
    float loss = 0.0f;

    if (cell < N_CELLS) {
        const float* base = pred + cell * (N_ANCHORS * N_CH);

        // IoU for each of 3 anchors
        float iou_a[N_ANCHORS];
        const float lx0 = l0 - l2 * 0.5f;
        const float ly0 = l1 - l3 * 0.5f;
        const float lx1 = l0 + l2 * 0.5f;
        const float ly1 = l1 + l3 * 0.5f;
        const float area_b = fabsf(l2 * l3);

        #pragma unroll
        for (int a = 0; a < N_ANCHORS; a++) {
            const float px = base[a * N_CH + 0];
            const float py = base[a * N_CH + 1];
            const float pw = base[a * N_CH + 2];
            const float ph = base[a * N_CH + 3];

            const float ax = fmaxf(px - pw * 0.5f, lx0);
            const float ay = fmaxf(py - ph * 0.5f, ly0);
            const float bx = fminf(px + pw * 0.5f, lx1);
            const float by = fminf(py + ph * 0.5f, ly1);

            const float inter = fabsf(fmaxf(bx - ax, 0.0f) * fmaxf(by - ay, 0.0f));
            const float area_a = fabsf(pw * ph);
            iou_a[a] = inter / (area_a + area_b - inter);
        }

        // argmax, first-max tie-break (strict >) to match jnp.argmax
        int   bi = 0;
        float best = iou_a[0];
        if (iou_a[1] > best) { best = iou_a[1]; bi = 1; }
        if (iou_a[2] > best) { best = iou_a[2]; bi = 2; }

        const float* b = base + bi * N_CH;
        const float b0 = b[0], b1 = b[1], b4 = b[4], b5 = b[5], b6 = b[6];

        // NOTE: wh_loss intentionally reuses indices 0/1 (x/y), replicating
        // the reference exactly.
        const float dx = l0 - b0;
        const float dy = l1 - b1;
        const float xy_loss = dx * dx + dy * dy;

        const float sx = sqrtf(l0) - sqrtf(b0);
        const float sy = sqrtf(l1) - sqrtf(b1);
        const float wh_loss = sx * sx + sy * sy;

        const float coord_loss = xy_loss + wh_loss;

        const bool has_obj = b4 > CONF_THRESH;

        const float d5 = l5 - b5;
        const float d6 = l6 - b6;
        const float class_loss = has_obj ? (d5 * d5 + d6 * d6) : 0.0f;

        const float dc = l4 - b4;
        const float conf_sq = dc * dc;
        const float conf_loss = has_obj ? conf_sq : NO_OBJECT * conf_sq;

        loss = coord_loss + class_loss + conf_loss;
    }

    // ---- block reduction: warp shuffle then smem across warps ----
    #pragma unroll
    for (int off = 16; off > 0; off >>= 1)
        loss += __shfl_down_sync(0xFFFFFFFFu, loss, off);

    __shared__ float warp_sums[32];
    const int lane = threadIdx.x & 31;
    const int warp = threadIdx.x >> 5;
    if (lane == 0) warp_sums[warp] = loss;
    __syncthreads();

    if (warp == 0) {
        float v = warp_sums[lane];   // blockDim = 1024 -> exactly 32 warps
        #pragma unroll
        for (int off = 16; off > 0; off >>= 1)
            v += __shfl_down_sync(0xFFFFFFFFu, v, off);
        if (lane == 0) out[0] = v;
    }
}

extern "C" void kernel_launch(void* const* d_in, const int* in_sizes, int n_in,
                              void* d_out, int out_size)
{
    const float* pred  = (const float*)d_in[0];
    const float* label = (const float*)d_in[1];
    float* out = (float*)d_out;
    yolo_loss_kernel<<<1, 1024>>>(pred, label, out);
}